// round 8
// baseline (speedup 1.0000x reference)
#include <cuda_runtime.h>

#define U_NODES 60000
#define I_NODES 40000
#define N_NODES 100000   // U + I
#define DIM     128
#define NV      32       // DIM/4 float4 per row
#define NEDGE   2000000

// ---------------- scratch (static device globals; no allocation) -------------
__device__ __align__(16) int   g_cntA[U_NODES];
__device__ __align__(16) int   g_cntB[I_NODES];
__device__ __align__(16) int   g_ptrA[U_NODES + 4];
__device__ __align__(16) int   g_ptrB[I_NODES + 4];
__device__ __align__(16) int   g_curA[U_NODES];
__device__ __align__(16) int   g_curB[I_NODES];
__device__ __align__(16) int   g_colA[NEDGE];
__device__ __align__(16) int   g_colB[NEDGE];
__device__ float g_embA[N_NODES * DIM];
__device__ float g_embB[N_NODES * DIM];
__device__ float g_acc [N_NODES * DIM];

// ---------------- kernels ----------------------------------------------------

__global__ void k_zero_counts() {
    int i = blockIdx.x * blockDim.x + threadIdx.x;
    if (i < U_NODES) g_cntA[i] = 0;
    if (i < I_NODES) g_cntB[i] = 0;
}

// 4 edges per thread, vectorized index loads; no-return atomicAdd -> RED
__global__ void k_count(const int4* __restrict__ u4, const int4* __restrict__ v4) {
    int i = blockIdx.x * blockDim.x + threadIdx.x;
    if (i >= NEDGE / 4) return;
    int4 a = u4[i], b = v4[i];
    atomicAdd(&g_cntA[a.x], 1); atomicAdd(&g_cntA[a.y], 1);
    atomicAdd(&g_cntA[a.z], 1); atomicAdd(&g_cntA[a.w], 1);
    atomicAdd(&g_cntB[b.x], 1); atomicAdd(&g_cntB[b.y], 1);
    atomicAdd(&g_cntB[b.z], 1); atomicAdd(&g_cntB[b.w], 1);
}

// Both exclusive scans in ONE launch: block 0 -> A (60000), block 1 -> B (40000).
// int4-vectorized loads of counts and int4 stores of ptr/cur.
__global__ void __launch_bounds__(1024) k_scan2() {
    const int which = blockIdx.x;
    const int  n  = which ? I_NODES : U_NODES;
    const int  n4 = n >> 2;
    const int4* cnt4 = reinterpret_cast<const int4*>(which ? g_cntB : g_cntA);
    int4* ptr4 = reinterpret_cast<int4*>(which ? g_ptrB : g_ptrA);
    int4* cur4 = reinterpret_cast<int4*>(which ? g_curB : g_curA);
    int*  ptr  = which ? g_ptrB : g_ptrA;

    __shared__ int sh[1024];
    int tid   = threadIdx.x;
    int chunk = (n4 + 1023) >> 10;
    int s0    = tid * chunk;
    int s1    = s0 + chunk; if (s1 > n4) s1 = n4;

    int s = 0;
    for (int i = s0; i < s1; i++) {
        int4 c = cnt4[i];
        s += c.x + c.y + c.z + c.w;
    }
    sh[tid] = s;
    __syncthreads();
    #pragma unroll
    for (int d = 1; d < 1024; d <<= 1) {
        int t = (tid >= d) ? sh[tid - d] : 0;
        __syncthreads();
        sh[tid] += t;
        __syncthreads();
    }
    int run = sh[tid] - s;  // exclusive prefix of this thread's chunk
    for (int i = s0; i < s1; i++) {
        int4 c = cnt4[i];
        int4 p;
        p.x = run;
        p.y = p.x + c.x;
        p.z = p.y + c.y;
        p.w = p.z + c.z;
        ptr4[i] = p;
        cur4[i] = p;
        run = p.w + c.w;
    }
    if (tid == 1023) ptr[n] = sh[1023];
}

__global__ void k_fill(const int4* __restrict__ u4, const int4* __restrict__ v4) {
    int i = blockIdx.x * blockDim.x + threadIdx.x;
    if (i >= NEDGE / 4) return;
    int4 a = u4[i], b = v4[i];
    g_colA[atomicAdd(&g_curA[a.x], 1)] = b.x;
    g_colA[atomicAdd(&g_curA[a.y], 1)] = b.y;
    g_colA[atomicAdd(&g_curA[a.z], 1)] = b.z;
    g_colA[atomicAdd(&g_curA[a.w], 1)] = b.w;
    g_colB[atomicAdd(&g_curB[b.x], 1)] = a.x;
    g_colB[atomicAdd(&g_curB[b.y], 1)] = a.y;
    g_colB[atomicAdd(&g_curB[b.z], 1)] = a.z;
    g_colB[atomicAdd(&g_curB[b.w], 1)] = a.w;
}

__device__ __forceinline__ void f4add(float4& a, const float4& b) {
    a.x += b.x; a.y += b.y; a.z += b.z; a.w += b.w;
}

// Gather over a CSR range from gsrc (rows all < U_NODES), unroll x8 for MLP.
__device__ __forceinline__ float4 gather_sum(const float4* __restrict__ gsrc,
                                             const int* __restrict__ col,
                                             int beg, int end, int lane) {
    float4 a = make_float4(0.f, 0.f, 0.f, 0.f);
    int j = beg;
    for (; j + 8 <= end; j += 8) {
        int c0 = col[j],     c1 = col[j + 1], c2 = col[j + 2], c3 = col[j + 3];
        int c4 = col[j + 4], c5 = col[j + 5], c6 = col[j + 6], c7 = col[j + 7];
        float4 e0 = gsrc[c0 * NV + lane];
        float4 e1 = gsrc[c1 * NV + lane];
        float4 e2 = gsrc[c2 * NV + lane];
        float4 e3 = gsrc[c3 * NV + lane];
        float4 e4 = gsrc[c4 * NV + lane];
        float4 e5 = gsrc[c5 * NV + lane];
        float4 e6 = gsrc[c6 * NV + lane];
        float4 e7 = gsrc[c7 * NV + lane];
        f4add(e0, e1); f4add(e2, e3); f4add(e4, e5); f4add(e6, e7);
        f4add(e0, e2); f4add(e4, e6);
        f4add(a, e0);  f4add(a, e4);
    }
    for (; j < end; j++) {
        float4 e = gsrc[col[j] * NV + lane];
        f4add(a, e);
    }
    return a;
}

// one warp per row; lane owns one float4 of the 128-wide feature vector.
// mode 0: first layer (gathers from ue; self row>=U from ie; acc = self+res)
// mode 1: middle layer (acc += res)
// mode 2: last layer  (out = (acc + res) * 0.25)
__global__ void __launch_bounds__(256) k_spmm(const float4* __restrict__ gsrc,
                                              const float4* __restrict__ isrc,
                                              int mode,
                                              float4* __restrict__ dst,
                                              float4* __restrict__ out) {
    float4* a4 = reinterpret_cast<float4*>(g_acc);

    int row  = (blockIdx.x * blockDim.x + threadIdx.x) >> 5;
    int lane = threadIdx.x & 31;

    float4 self = (mode == 0 && row >= U_NODES)
                    ? isrc[(row - U_NODES) * NV + lane]
                    : gsrc[row * NV + lane];
    float4 res;

    if (row < U_NODES) {
        // edge set A: rows = u_id, cols = v_id (<40000), scale 1/u_deg[row]
        int beg = g_ptrA[row], end = g_ptrA[row + 1];
        float4 a = gather_sum(gsrc, g_colA, beg, end, lane);
        float invA = 1.0f / (float)(end - beg + 1);   // u_deg = cnt + 1
        res.x = invA * (a.x + self.x);
        res.y = invA * (a.y + self.y);
        res.z = invA * (a.z + self.z);
        res.w = invA * (a.w + self.w);

        if (row < I_NODES) {
            // edge set B: rows = v_id, cols = u_id (<60000), scale 1/v_deg[row]
            int bb = g_ptrB[row], be = g_ptrB[row + 1];
            float4 b = gather_sum(gsrc, g_colB, bb, be, lane);
            float invB = 1.0f / (float)(be - bb + 1);
            res.x += invB * b.x;
            res.y += invB * b.y;
            res.z += invB * b.z;
            res.w += invB * b.w;
        }
    } else {
        // item nodes >= U get only the self loop (source has no column offset)
        int v = row - U_NODES;
        float invB = 1.0f / (float)(g_ptrB[v + 1] - g_ptrB[v] + 1);
        res.x = invB * self.x;
        res.y = invB * self.y;
        res.z = invB * self.z;
        res.w = invB * self.w;
    }

    int idx = row * NV + lane;
    if (mode == 0) {
        // acc starts at emb0 (= self) plus layer-1 result
        a4[idx] = make_float4(self.x + res.x, self.y + res.y,
                              self.z + res.z, self.w + res.w);
        dst[idx] = res;
    } else if (mode == 1) {
        float4 acc = a4[idx];
        f4add(acc, res);
        a4[idx] = acc;
        dst[idx] = res;
    } else {
        float4 acc = a4[idx];
        out[idx] = make_float4((acc.x + res.x) * 0.25f, (acc.y + res.y) * 0.25f,
                               (acc.z + res.z) * 0.25f, (acc.w + res.w) * 0.25f);
    }
}

// ---------------- launch ------------------------------------------------------

extern "C" void kernel_launch(void* const* d_in, const int* in_sizes, int n_in,
                              void* d_out, int out_size) {
    const float4* ue = (const float4*)d_in[0];   // user_embedding [U, D] f32
    const float4* ie = (const float4*)d_in[1];   // item_embedding [I, D] f32
    const int4*   u4 = (const int4*)d_in[2];     // u_id [E] i32
    const int4*   v4 = (const int4*)d_in[3];     // v_id [E] i32
    float4*       out = (float4*)d_out;          // [N, D] f32

    float4* embA = reinterpret_cast<float4*>(g_embA);
    float4* embB = reinterpret_cast<float4*>(g_embB);

    const int edge_blocks = (NEDGE / 4 + 255) / 256;
    const int spmm_blocks = (N_NODES * 32) / 256;  // exact: 12500

    // 1) CSR build (reused across all 3 layers)
    k_zero_counts<<<(U_NODES + 255) / 256, 256>>>();
    k_count<<<edge_blocks, 256>>>(u4, v4);
    k_scan2<<<2, 1024>>>();                       // both scans in parallel
    k_fill<<<edge_blocks, 256>>>(u4, v4);

    // 2) three propagation layers; init fused into layer 1, mean into layer 3
    k_spmm<<<spmm_blocks, 256>>>(ue,   ie, 0, embA, out);
    k_spmm<<<spmm_blocks, 256>>>(embA, ie, 1, embB, out);
    k_spmm<<<spmm_blocks, 256>>>(embB, ie, 2, embA, out);
}

// round 9
// speedup vs baseline: 46.0477x; 46.0477x over previous
#include <cuda_runtime.h>

#define U_NODES 60000
#define I_NODES 40000
#define N_NODES 100000   // U + I
#define DIM     128
#define NV      32       // DIM/4 float4 per row
#define NEDGE   2000000

// ---------------- scratch (static device globals; no allocation) -------------
__device__ __align__(16) int   g_cntA[U_NODES];
__device__ __align__(16) int   g_cntB[I_NODES];
__device__ __align__(16) int   g_ptrA[U_NODES + 4];
__device__ __align__(16) int   g_ptrB[I_NODES + 4];
__device__ __align__(16) int   g_curA[U_NODES];
__device__ __align__(16) int   g_curB[I_NODES];
__device__ __align__(16) int   g_colA[NEDGE];
__device__ __align__(16) int   g_colB[NEDGE];
__device__ __align__(16) float g_embA[N_NODES * DIM];
__device__ __align__(16) float g_embB[N_NODES * DIM];
__device__ __align__(16) float g_acc [N_NODES * DIM];

// ---------------- kernels ----------------------------------------------------

__global__ void k_zero_counts() {
    int i = blockIdx.x * blockDim.x + threadIdx.x;
    if (i < U_NODES) g_cntA[i] = 0;
    if (i < I_NODES) g_cntB[i] = 0;
}

// 4 edges per thread, vectorized index loads; no-return atomicAdd -> RED
__global__ void k_count(const int4* __restrict__ u4, const int4* __restrict__ v4) {
    int i = blockIdx.x * blockDim.x + threadIdx.x;
    if (i >= NEDGE / 4) return;
    int4 a = u4[i], b = v4[i];
    atomicAdd(&g_cntA[a.x], 1); atomicAdd(&g_cntA[a.y], 1);
    atomicAdd(&g_cntA[a.z], 1); atomicAdd(&g_cntA[a.w], 1);
    atomicAdd(&g_cntB[b.x], 1); atomicAdd(&g_cntB[b.y], 1);
    atomicAdd(&g_cntB[b.z], 1); atomicAdd(&g_cntB[b.w], 1);
}

// Both exclusive scans in ONE launch: block 0 -> A (60000), block 1 -> B (40000).
__global__ void __launch_bounds__(1024) k_scan2() {
    const int which = blockIdx.x;
    const int  n  = which ? I_NODES : U_NODES;
    const int  n4 = n >> 2;
    const int4* cnt4 = reinterpret_cast<const int4*>(which ? g_cntB : g_cntA);
    int4* ptr4 = reinterpret_cast<int4*>(which ? g_ptrB : g_ptrA);
    int4* cur4 = reinterpret_cast<int4*>(which ? g_curB : g_curA);
    int*  ptr  = which ? g_ptrB : g_ptrA;

    __shared__ int sh[1024];
    int tid   = threadIdx.x;
    int chunk = (n4 + 1023) >> 10;
    int s0    = tid * chunk;
    int s1    = s0 + chunk; if (s1 > n4) s1 = n4;

    int s = 0;
    for (int i = s0; i < s1; i++) {
        int4 c = cnt4[i];
        s += c.x + c.y + c.z + c.w;
    }
    sh[tid] = s;
    __syncthreads();
    #pragma unroll
    for (int d = 1; d < 1024; d <<= 1) {
        int t = (tid >= d) ? sh[tid - d] : 0;
        __syncthreads();
        sh[tid] += t;
        __syncthreads();
    }
    int run = sh[tid] - s;  // exclusive prefix of this thread's chunk
    for (int i = s0; i < s1; i++) {
        int4 c = cnt4[i];
        int4 p;
        p.x = run;
        p.y = p.x + c.x;
        p.z = p.y + c.y;
        p.w = p.z + c.z;
        ptr4[i] = p;
        cur4[i] = p;
        run = p.w + c.w;
    }
    if (tid == 1023) ptr[n] = sh[1023];
}

__global__ void k_fill(const int4* __restrict__ u4, const int4* __restrict__ v4) {
    int i = blockIdx.x * blockDim.x + threadIdx.x;
    if (i >= NEDGE / 4) return;
    int4 a = u4[i], b = v4[i];
    g_colA[atomicAdd(&g_curA[a.x], 1)] = b.x;
    g_colA[atomicAdd(&g_curA[a.y], 1)] = b.y;
    g_colA[atomicAdd(&g_curA[a.z], 1)] = b.z;
    g_colA[atomicAdd(&g_curA[a.w], 1)] = b.w;
    g_colB[atomicAdd(&g_curB[b.x], 1)] = a.x;
    g_colB[atomicAdd(&g_curB[b.y], 1)] = a.y;
    g_colB[atomicAdd(&g_curB[b.z], 1)] = a.z;
    g_colB[atomicAdd(&g_curB[b.w], 1)] = a.w;
}

__device__ __forceinline__ void f4add(float4& a, const float4& b) {
    a.x += b.x; a.y += b.y; a.z += b.z; a.w += b.w;
}

// Gather over a CSR range from gsrc (all source rows < U_NODES), unroll x8 for MLP.
__device__ __forceinline__ float4 gather_sum(const float4* __restrict__ gsrc,
                                             const int* __restrict__ col,
                                             int beg, int end, int lane) {
    float4 a = make_float4(0.f, 0.f, 0.f, 0.f);
    int j = beg;
    for (; j + 8 <= end; j += 8) {
        int c0 = col[j],     c1 = col[j + 1], c2 = col[j + 2], c3 = col[j + 3];
        int c4 = col[j + 4], c5 = col[j + 5], c6 = col[j + 6], c7 = col[j + 7];
        float4 e0 = gsrc[c0 * NV + lane];
        float4 e1 = gsrc[c1 * NV + lane];
        float4 e2 = gsrc[c2 * NV + lane];
        float4 e3 = gsrc[c3 * NV + lane];
        float4 e4 = gsrc[c4 * NV + lane];
        float4 e5 = gsrc[c5 * NV + lane];
        float4 e6 = gsrc[c6 * NV + lane];
        float4 e7 = gsrc[c7 * NV + lane];
        f4add(e0, e1); f4add(e2, e3); f4add(e4, e5); f4add(e6, e7);
        f4add(e0, e2); f4add(e4, e6);
        f4add(a, e0);  f4add(a, e4);
    }
    for (; j < end; j++) {
        float4 e = gsrc[col[j] * NV + lane];
        f4add(a, e);
    }
    return a;
}

// one warp per row; lane owns one float4 of the 128-wide feature vector.
// mode 0: layer 1 (gather from ue; self row>=U from ie; acc = self + res; dst = embA)
// mode 1: layer 2 (gather from embA; acc += res; dst = embB)
// mode 2: layer 3 (gather from embB; out = (acc + res) * 0.25)
// NOTE: g_embA/g_embB are resolved HERE, in device code — passing their host-side
// shadow addresses from kernel_launch routes all traffic through ATS host memory
// over NVLink-C2C (the R8 36x regression).
__global__ void __launch_bounds__(256) k_spmm(const float4* __restrict__ ue,
                                              const float4* __restrict__ ie,
                                              int mode,
                                              float4* __restrict__ out) {
    float4* a4 = reinterpret_cast<float4*>(g_acc);

    const float4* gsrc;
    float4*       dst;
    if (mode == 0)      { gsrc = ue;                                         dst = reinterpret_cast<float4*>(g_embA); }
    else if (mode == 1) { gsrc = reinterpret_cast<const float4*>(g_embA);    dst = reinterpret_cast<float4*>(g_embB); }
    else                { gsrc = reinterpret_cast<const float4*>(g_embB);    dst = nullptr; }

    int row  = (blockIdx.x * blockDim.x + threadIdx.x) >> 5;
    int lane = threadIdx.x & 31;

    float4 self = (mode == 0 && row >= U_NODES)
                    ? ie[(row - U_NODES) * NV + lane]
                    : gsrc[row * NV + lane];
    float4 res;

    if (row < U_NODES) {
        // edge set A: rows = u_id, cols = v_id (<40000), scale 1/u_deg[row]
        int beg = g_ptrA[row], end = g_ptrA[row + 1];
        float4 a = gather_sum(gsrc, g_colA, beg, end, lane);
        float invA = 1.0f / (float)(end - beg + 1);   // u_deg = cnt + 1
        res.x = invA * (a.x + self.x);
        res.y = invA * (a.y + self.y);
        res.z = invA * (a.z + self.z);
        res.w = invA * (a.w + self.w);

        if (row < I_NODES) {
            // edge set B: rows = v_id, cols = u_id (<60000), scale 1/v_deg[row]
            int bb = g_ptrB[row], be = g_ptrB[row + 1];
            float4 b = gather_sum(gsrc, g_colB, bb, be, lane);
            float invB = 1.0f / (float)(be - bb + 1);
            res.x += invB * b.x;
            res.y += invB * b.y;
            res.z += invB * b.z;
            res.w += invB * b.w;
        }
    } else {
        // item nodes >= U get only the self loop (source has no column offset)
        int v = row - U_NODES;
        float invB = 1.0f / (float)(g_ptrB[v + 1] - g_ptrB[v] + 1);
        res.x = invB * self.x;
        res.y = invB * self.y;
        res.z = invB * self.z;
        res.w = invB * self.w;
    }

    int idx = row * NV + lane;
    if (mode == 0) {
        a4[idx] = make_float4(self.x + res.x, self.y + res.y,
                              self.z + res.z, self.w + res.w);
        dst[idx] = res;
    } else if (mode == 1) {
        float4 acc = a4[idx];
        f4add(acc, res);
        a4[idx] = acc;
        dst[idx] = res;
    } else {
        float4 acc = a4[idx];
        out[idx] = make_float4((acc.x + res.x) * 0.25f, (acc.y + res.y) * 0.25f,
                               (acc.z + res.z) * 0.25f, (acc.w + res.w) * 0.25f);
    }
}

// ---------------- launch ------------------------------------------------------

extern "C" void kernel_launch(void* const* d_in, const int* in_sizes, int n_in,
                              void* d_out, int out_size) {
    const float4* ue = (const float4*)d_in[0];   // user_embedding [U, D] f32
    const float4* ie = (const float4*)d_in[1];   // item_embedding [I, D] f32
    const int4*   u4 = (const int4*)d_in[2];     // u_id [E] i32
    const int4*   v4 = (const int4*)d_in[3];     // v_id [E] i32
    float4*       out = (float4*)d_out;          // [N, D] f32

    const int edge_blocks = (NEDGE / 4 + 255) / 256;
    const int spmm_blocks = (N_NODES * 32) / 256;  // exact: 12500

    // 1) CSR build (reused across all 3 layers)
    k_zero_counts<<<(U_NODES + 255) / 256, 256>>>();
    k_count<<<edge_blocks, 256>>>(u4, v4);
    k_scan2<<<2, 1024>>>();                       // both scans in parallel
    k_fill<<<edge_blocks, 256>>>(u4, v4);

    // 2) three propagation layers; init fused into layer 1, mean into layer 3
    k_spmm<<<spmm_blocks, 256>>>(ue, ie, 0, out);
    k_spmm<<<spmm_blocks, 256>>>(ue, ie, 1, out);
    k_spmm<<<spmm_blocks, 256>>>(ue, ie, 2, out);
}

// round 11
// speedup vs baseline: 56.0221x; 1.2166x over previous
#include <cuda_runtime.h>
#include <cuda_fp16.h>

#define U_NODES 60000
#define I_NODES 40000
#define N_NODES 100000   // U + I
#define DIM     128
#define NV      32       // DIM/4 float4 (or DIM/4 uint2 for half) per row
#define NEDGE   2000000

// ---------------- scratch (static device globals; no allocation) -------------
__device__ __align__(16) int   g_cntA[U_NODES];
__device__ __align__(16) int   g_cntB[I_NODES];
__device__ __align__(16) int   g_ptrA[U_NODES + 4];
__device__ __align__(16) int   g_ptrB[I_NODES + 4];
__device__ __align__(16) int   g_slotA[NEDGE];
__device__ __align__(16) int   g_slotB[NEDGE];
__device__ __align__(16) int   g_colA[NEDGE];
__device__ __align__(16) int   g_colB[NEDGE];
__device__ __align__(16) __half g_h0[U_NODES * DIM];   // half copy of user rows (layer-1 gather src)
__device__ __align__(16) __half g_h1[N_NODES * DIM];   // layer-1 output (half)
__device__ __align__(16) __half g_h2[N_NODES * DIM];   // layer-2 output (half)
__device__ __align__(16) float g_acc[N_NODES * DIM];   // fp32 running sum of layer snapshots

// ---------------- half <-> float4 helpers ------------------------------------

__device__ __forceinline__ float4 h2f4(uint2 h) {
    __half2 lo = *reinterpret_cast<__half2*>(&h.x);
    __half2 hi = *reinterpret_cast<__half2*>(&h.y);
    float2 f0 = __half22float2(lo);
    float2 f1 = __half22float2(hi);
    return make_float4(f0.x, f0.y, f1.x, f1.y);
}

__device__ __forceinline__ uint2 f4h(float4 v) {
    __half2 lo = __floats2half2_rn(v.x, v.y);
    __half2 hi = __floats2half2_rn(v.z, v.w);
    uint2 r;
    r.x = *reinterpret_cast<unsigned*>(&lo);
    r.y = *reinterpret_cast<unsigned*>(&hi);
    return r;
}

__device__ __forceinline__ void f4add(float4& a, const float4& b) {
    a.x += b.x; a.y += b.y; a.z += b.z; a.w += b.w;
}

// ---------------- CSR build ---------------------------------------------------

__global__ void k_zero_counts() {
    int i = blockIdx.x * blockDim.x + threadIdx.x;
    if (i < U_NODES) g_cntA[i] = 0;
    if (i < I_NODES) g_cntB[i] = 0;
}

// 4 edges per thread; atomic RETURNS the per-row slot -> recorded for atomic-free fill
__global__ void k_count(const int4* __restrict__ u4, const int4* __restrict__ v4) {
    int i = blockIdx.x * blockDim.x + threadIdx.x;
    if (i >= NEDGE / 4) return;
    int4 a = u4[i], b = v4[i];
    int4 sa, sb;
    sa.x = atomicAdd(&g_cntA[a.x], 1);
    sa.y = atomicAdd(&g_cntA[a.y], 1);
    sa.z = atomicAdd(&g_cntA[a.z], 1);
    sa.w = atomicAdd(&g_cntA[a.w], 1);
    sb.x = atomicAdd(&g_cntB[b.x], 1);
    sb.y = atomicAdd(&g_cntB[b.y], 1);
    sb.z = atomicAdd(&g_cntB[b.z], 1);
    sb.w = atomicAdd(&g_cntB[b.w], 1);
    reinterpret_cast<int4*>(g_slotA)[i] = sa;
    reinterpret_cast<int4*>(g_slotB)[i] = sb;
}

// Both exclusive scans in ONE launch: block 0 -> A (60000), block 1 -> B (40000).
__global__ void __launch_bounds__(1024) k_scan2() {
    const int which = blockIdx.x;
    const int  n  = which ? I_NODES : U_NODES;
    const int  n4 = n >> 2;
    const int4* cnt4 = reinterpret_cast<const int4*>(which ? g_cntB : g_cntA);
    int4* ptr4 = reinterpret_cast<int4*>(which ? g_ptrB : g_ptrA);
    int*  ptr  = which ? g_ptrB : g_ptrA;

    __shared__ int sh[1024];
    int tid   = threadIdx.x;
    int chunk = (n4 + 1023) >> 10;
    int s0    = tid * chunk;
    int s1    = s0 + chunk; if (s1 > n4) s1 = n4;

    int s = 0;
    for (int i = s0; i < s1; i++) {
        int4 c = cnt4[i];
        s += c.x + c.y + c.z + c.w;
    }
    sh[tid] = s;
    __syncthreads();
    #pragma unroll
    for (int d = 1; d < 1024; d <<= 1) {
        int t = (tid >= d) ? sh[tid - d] : 0;
        __syncthreads();
        sh[tid] += t;
        __syncthreads();
    }
    int run = sh[tid] - s;  // exclusive prefix of this thread's chunk
    for (int i = s0; i < s1; i++) {
        int4 c = cnt4[i];
        int4 p;
        p.x = run;
        p.y = p.x + c.x;
        p.z = p.y + c.y;
        p.w = p.z + c.z;
        ptr4[i] = p;
        run = p.w + c.w;
    }
    if (tid == 1023) ptr[n] = sh[1023];
}

// Atomic-free fill: position = ptr[row] + recorded slot. Pure high-MLP scatter.
__global__ void k_fill(const int4* __restrict__ u4, const int4* __restrict__ v4) {
    int i = blockIdx.x * blockDim.x + threadIdx.x;
    if (i >= NEDGE / 4) return;
    int4 a = u4[i], b = v4[i];
    int4 sa = reinterpret_cast<const int4*>(g_slotA)[i];
    int4 sb = reinterpret_cast<const int4*>(g_slotB)[i];
    g_colA[g_ptrA[a.x] + sa.x] = b.x;
    g_colA[g_ptrA[a.y] + sa.y] = b.y;
    g_colA[g_ptrA[a.z] + sa.z] = b.z;
    g_colA[g_ptrA[a.w] + sa.w] = b.w;
    g_colB[g_ptrB[b.x] + sb.x] = a.x;
    g_colB[g_ptrB[b.y] + sb.y] = a.y;
    g_colB[g_ptrB[b.z] + sb.z] = a.z;
    g_colB[g_ptrB[b.w] + sb.w] = a.w;
}

// Convert user rows of the input embedding to half (layer-1 gather source).
__global__ void k_tohalf(const float4* __restrict__ ue) {
    int i = blockIdx.x * blockDim.x + threadIdx.x;
    if (i >= U_NODES * NV) return;
    reinterpret_cast<uint2*>(g_h0)[i] = f4h(ue[i]);
}

// ---------------- SpMM --------------------------------------------------------

// Gather-sum over a CSR range from half source (all source rows < U_NODES).
// Lane loads one uint2 (4 halves) per source row; unroll x8 for MLP.
__device__ __forceinline__ float4 gather_sum_h(const uint2* __restrict__ gh,
                                               const int* __restrict__ col,
                                               int beg, int end, int lane) {
    float4 a = make_float4(0.f, 0.f, 0.f, 0.f);
    int j = beg;
    for (; j + 8 <= end; j += 8) {
        int c0 = col[j],     c1 = col[j + 1], c2 = col[j + 2], c3 = col[j + 3];
        int c4 = col[j + 4], c5 = col[j + 5], c6 = col[j + 6], c7 = col[j + 7];
        uint2 h0 = gh[c0 * NV + lane];
        uint2 h1 = gh[c1 * NV + lane];
        uint2 h2 = gh[c2 * NV + lane];
        uint2 h3 = gh[c3 * NV + lane];
        uint2 h4 = gh[c4 * NV + lane];
        uint2 h5 = gh[c5 * NV + lane];
        uint2 h6 = gh[c6 * NV + lane];
        uint2 h7 = gh[c7 * NV + lane];
        float4 e0 = h2f4(h0), e1 = h2f4(h1), e2 = h2f4(h2), e3 = h2f4(h3);
        float4 e4 = h2f4(h4), e5 = h2f4(h5), e6 = h2f4(h6), e7 = h2f4(h7);
        f4add(e0, e1); f4add(e2, e3); f4add(e4, e5); f4add(e6, e7);
        f4add(e0, e2); f4add(e4, e6);
        f4add(a, e0);  f4add(a, e4);
    }
    for (; j < end; j++) {
        float4 e = h2f4(gh[col[j] * NV + lane]);
        f4add(a, e);
    }
    return a;
}

// one warp per row; lane owns 4 of the 128 features.
// mode 0: gather g_h0 (half of ue); self fp32 from ue/ie; acc = self + res; dst = g_h1
// mode 1: gather g_h1; self = g_h1[row];                  acc += res;       dst = g_h2
// mode 2: gather g_h2; self = g_h2[row];                  out = (acc + res) * 0.25
// NOTE: device symbols resolved HERE — host-side shadow addresses route through
// ATS host memory over NVLink-C2C (the R8 36x regression).
__global__ void __launch_bounds__(256) k_spmm(const float4* __restrict__ ue,
                                              const float4* __restrict__ ie,
                                              int mode,
                                              float4* __restrict__ out) {
    float4* a4 = reinterpret_cast<float4*>(g_acc);

    const uint2* gh;
    uint2*       dsth;
    if (mode == 0)      { gh = reinterpret_cast<const uint2*>(g_h0); dsth = reinterpret_cast<uint2*>(g_h1); }
    else if (mode == 1) { gh = reinterpret_cast<const uint2*>(g_h1); dsth = reinterpret_cast<uint2*>(g_h2); }
    else                { gh = reinterpret_cast<const uint2*>(g_h2); dsth = nullptr; }

    int row  = (blockIdx.x * blockDim.x + threadIdx.x) >> 5;
    int lane = threadIdx.x & 31;

    float4 self;
    if (mode == 0) {
        self = (row < U_NODES) ? ue[row * NV + lane]
                               : ie[(row - U_NODES) * NV + lane];
    } else {
        self = h2f4(gh[row * NV + lane]);
    }

    float4 res;
    if (row < U_NODES) {
        // edge set A: rows = u_id, cols = v_id (<40000), scale 1/u_deg[row]
        int beg = g_ptrA[row], end = g_ptrA[row + 1];
        float4 a = gather_sum_h(gh, g_colA, beg, end, lane);
        float invA = 1.0f / (float)(end - beg + 1);   // u_deg = cnt + 1
        res.x = invA * (a.x + self.x);
        res.y = invA * (a.y + self.y);
        res.z = invA * (a.z + self.z);
        res.w = invA * (a.w + self.w);

        if (row < I_NODES) {
            // edge set B: rows = v_id, cols = u_id (<60000), scale 1/v_deg[row]
            int bb = g_ptrB[row], be = g_ptrB[row + 1];
            float4 b = gather_sum_h(gh, g_colB, bb, be, lane);
            float invB = 1.0f / (float)(be - bb + 1);
            res.x += invB * b.x;
            res.y += invB * b.y;
            res.z += invB * b.z;
            res.w += invB * b.w;
        }
    } else {
        // item nodes >= U get only the self loop (source has no column offset)
        int v = row - U_NODES;
        float invB = 1.0f / (float)(g_ptrB[v + 1] - g_ptrB[v] + 1);
        res.x = invB * self.x;
        res.y = invB * self.y;
        res.z = invB * self.z;
        res.w = invB * self.w;
    }

    int idx = row * NV + lane;
    if (mode == 0) {
        a4[idx] = make_float4(self.x + res.x, self.y + res.y,
                              self.z + res.z, self.w + res.w);
        dsth[idx] = f4h(res);
    } else if (mode == 1) {
        float4 acc = a4[idx];
        f4add(acc, res);
        a4[idx] = acc;
        dsth[idx] = f4h(res);
    } else {
        float4 acc = a4[idx];
        out[idx] = make_float4((acc.x + res.x) * 0.25f, (acc.y + res.y) * 0.25f,
                               (acc.z + res.z) * 0.25f, (acc.w + res.w) * 0.25f);
    }
}

// ---------------- launch ------------------------------------------------------

extern "C" void kernel_launch(void* const* d_in, const int* in_sizes, int n_in,
                              void* d_out, int out_size) {
    const float4* ue = (const float4*)d_in[0];   // user_embedding [U, D] f32
    const float4* ie = (const float4*)d_in[1];   // item_embedding [I, D] f32
    const int4*   u4 = (const int4*)d_in[2];     // u_id [E] i32
    const int4*   v4 = (const int4*)d_in[3];     // v_id [E] i32
    float4*       out = (float4*)d_out;          // [N, D] f32

    const int edge_blocks = (NEDGE / 4 + 255) / 256;
    const int spmm_blocks = (N_NODES * 32) / 256;  // exact: 12500

    // 1) CSR build (slot-recording count -> atomic-free fill)
    k_zero_counts<<<(U_NODES + 255) / 256, 256>>>();
    k_count<<<edge_blocks, 256>>>(u4, v4);
    k_scan2<<<2, 1024>>>();
    k_fill<<<edge_blocks, 256>>>(u4, v4);

    // 2) half-precision copy of user rows for layer-1 gathers
    k_tohalf<<<(U_NODES * NV + 255) / 256, 256>>>(ue);

    // 3) three propagation layers; init fused into layer 1, mean into layer 3
    k_spmm<<<spmm_blocks, 256>>>(ue, ie, 0, out);
    k_spmm<<<spmm_blocks, 256>>>(ue, ie, 1, out);
    k_spmm<<<spmm_blocks, 256>>>(ue, ie, 2, out);
}